// round 1
// baseline (speedup 1.0000x reference)
#include <cuda_runtime.h>

// Problem constants
#define BB   256     // batch
#define TT   256     // timesteps
#define KTOK 128     // latent / token dim
#define HH   512     // hidden
#define G4H  2048    // 4*H
#define DD   128     // output dim

#define NCTA 128
#define NTHR 256
#define BK   16
#define NKC  (HH / BK)   // 32 k-chunks
#define SGP  68          // padded pitch for A tile / gates tile

// Persistent state (device globals: allocation-free scratch)
__device__ float g_h[2][BB * HH];
__device__ unsigned int g_bar;

__global__ void lstm_reset_kernel() { g_bar = 0u; }

// ---- packed f32x2 helpers --------------------------------------------------
__device__ __forceinline__ unsigned long long pk2(float x, float y) {
    unsigned long long r;
    asm("mov.b64 %0, {%1,%2};" : "=l"(r) : "f"(x), "f"(y));
    return r;
}
__device__ __forceinline__ void upk2(unsigned long long v, float& x, float& y) {
    asm("mov.b64 {%0,%1}, %2;" : "=f"(x), "=f"(y) : "l"(v));
}
#define FFMA2(d, a, b) asm("fma.rn.f32x2 %0, %1, %2, %0;" : "+l"(d) : "l"(a), "l"(b))

__device__ __forceinline__ float sigm(float x)  { return 1.f / (1.f + __expf(-x)); }
__device__ __forceinline__ float tanhx(float x) { return 2.f / (1.f + __expf(-2.f * x)) - 1.f; }

// ---- grid-wide barrier (all 128 CTAs co-resident) ---------------------------
__device__ __forceinline__ void gridbar() {
    __syncthreads();
    if (threadIdx.x == 0) {
        __threadfence();
        unsigned int t = atomicAdd(&g_bar, 1u);
        unsigned int target = (t / NCTA + 1u) * NCTA;
        while (*(volatile unsigned int*)&g_bar < target) __nanosleep(64);
        __threadfence();
    }
    __syncthreads();
}

__global__ void __launch_bounds__(NTHR, 1) lstm_kernel(
    const float* __restrict__ z,     const float* __restrict__ Wz,
    const float* __restrict__ bz,    const float* __restrict__ token,
    const float* __restrict__ Wi,    const float* __restrict__ Wh,
    const float* __restrict__ bh,    const float* __restrict__ Wout,
    const float* __restrict__ bout,  float* __restrict__ out)
{
    __shared__ float sA[2][BK][SGP];     // h tile, stored [k][m], padded
    __shared__ float sB[2][BK][64];      // Wh tile, [k][n]
    __shared__ float sg[64 * SGP];       // gates tile for cell update
    __shared__ float sWo[2][64];         // Wout chunk: [k(16)][d(4)]
    __shared__ float sxg[64];            // token@Wi + bh for this CTA's 64 gate cols
    __shared__ float stok[KTOK];

    const int tid = threadIdx.x;
    const int mt  = blockIdx.x & 3;      // batch tile (4 of 64 rows)
    const int jt  = blockIdx.x >> 2;     // hidden tile (32 of 16 units)
    const int m0  = mt * 64;

    const int tx  = tid & 15,  ty  = tid >> 4;
    const int tx4 = tx * 4,    ty4 = ty * 4;

    // A loader: thread -> (row, k-quad)
    const int lam = tid >> 2;            // 0..63
    const int lak = (tid & 3) * 4;       // 0,4,8,12
    // B loader: thread -> (k, col-quad)
    const int lbk = tid >> 4;            // 0..15
    const int lbn = tid & 15;            // col group of 4
    const int lbcol = (lbn >> 2) * HH + jt * 16 + (lbn & 3) * 4;  // Wh column
    // Wo loader (tid < 64): k = tid>>2, d = tid&3
    const int lwk = tid >> 2, lwd = tid & 3;
    // output element owned by this thread
    const int om = tid >> 2;             // local row 0..63
    const int od = tid & 3;              // local D col 0..3
    // cell-update mapping: (rows mq*4+r, hidden unit jj)
    const int jj = tid & 15;
    const int mq = tid >> 4;             // 0..15

    // ================= init: x_gates slice and h0 tile =================
    if (tid < KTOK) stok[tid] = token[tid];
    __syncthreads();

    if (tid < 64) {
        int col = (tid >> 4) * HH + jt * 16 + (tid & 15);
        float s = bh[col];
        #pragma unroll 4
        for (int k = 0; k < KTOK; ++k)
            s = fmaf(stok[k], __ldg(&Wi[k * G4H + col]), s);
        sxg[tid] = s;
    }
    {
        int j = jt * 16 + jj;
        float b = bz[j];
        float a0 = b, a1 = b, a2 = b, a3 = b;
        const float* zr = z + (size_t)(m0 + mq * 4) * KTOK;
        #pragma unroll 4
        for (int k = 0; k < KTOK; ++k) {
            float w = __ldg(&Wz[k * HH + j]);
            a0 = fmaf(__ldg(zr + k),            w, a0);
            a1 = fmaf(__ldg(zr + KTOK + k),     w, a1);
            a2 = fmaf(__ldg(zr + 2 * KTOK + k), w, a2);
            a3 = fmaf(__ldg(zr + 3 * KTOK + k), w, a3);
        }
        float* hp = &g_h[0][(size_t)(m0 + mq * 4) * HH + j];
        __stcg(hp,          fmaxf(a0, 0.f));
        __stcg(hp + HH,     fmaxf(a1, 0.f));
        __stcg(hp + 2 * HH, fmaxf(a2, 0.f));
        __stcg(hp + 3 * HH, fmaxf(a3, 0.f));
    }
    float cc0 = 0.f, cc1 = 0.f, cc2 = 0.f, cc3 = 0.f;  // cell state, register-resident
    gridbar();

    // ================= main sequential loop =================
    // Iteration t: gates GEMM on h_t (carry) -> h_{t+1}; fused out_{t-1} = h_t @ Wo_{t-1}.
    // Extra iteration t == TT computes only out_{TT-1}.
    for (int t = 0; t <= TT; ++t) {
        const float* hc = g_h[t & 1];
        const int te = (t == 0) ? 0 : t - 1;
        const float* Wo = Wout + (size_t)te * HH * DD + jt * 4;

        unsigned long long a00 = 0, a01 = 0, a10 = 0, a11 = 0,
                           a20 = 0, a21 = 0, a30 = 0, a31 = 0;
        float oacc = 0.f;

        // prologue: chunk 0
        float4 rA = __ldcg((const float4*)(hc + (size_t)(m0 + lam) * HH + lak));
        float4 rB = __ldg((const float4*)(Wh + (size_t)lbk * G4H + lbcol));
        float  rW = (tid < 64) ? __ldg(Wo + lwk * DD + lwd) : 0.f;
        sA[0][lak + 0][lam] = rA.x;  sA[0][lak + 1][lam] = rA.y;
        sA[0][lak + 2][lam] = rA.z;  sA[0][lak + 3][lam] = rA.w;
        *(float4*)&sB[0][lbk][lbn * 4] = rB;
        if (tid < 64) sWo[0][tid] = rW;
        __syncthreads();

        #pragma unroll 1
        for (int kc = 0; kc < NKC; ++kc) {
            const int buf = kc & 1;
            if (kc + 1 < NKC) {
                const int k0 = (kc + 1) * BK;
                rA = __ldcg((const float4*)(hc + (size_t)(m0 + lam) * HH + k0 + lak));
                rB = __ldg((const float4*)(Wh + (size_t)(k0 + lbk) * G4H + lbcol));
                if (tid < 64) rW = __ldg(Wo + (k0 + lwk) * DD + lwd);
            }
            #pragma unroll
            for (int k = 0; k < BK; ++k) {
                const float* pa = &sA[buf][k][0];
                float4 av = *(const float4*)(pa + ty4);
                float4 bv = *(const float4*)(&sB[buf][k][tx4]);
                unsigned long long b01 = pk2(bv.x, bv.y);
                unsigned long long b23 = pk2(bv.z, bv.w);
                unsigned long long aa;
                aa = pk2(av.x, av.x); FFMA2(a00, aa, b01); FFMA2(a01, aa, b23);
                aa = pk2(av.y, av.y); FFMA2(a10, aa, b01); FFMA2(a11, aa, b23);
                aa = pk2(av.z, av.z); FFMA2(a20, aa, b01); FFMA2(a21, aa, b23);
                aa = pk2(av.w, av.w); FFMA2(a30, aa, b01); FFMA2(a31, aa, b23);
                oacc = fmaf(pa[om], sWo[buf][k * 4 + od], oacc);  // fused out-proj
            }
            if (kc + 1 < NKC) {
                const int nb = buf ^ 1;
                sA[nb][lak + 0][lam] = rA.x;  sA[nb][lak + 1][lam] = rA.y;
                sA[nb][lak + 2][lam] = rA.z;  sA[nb][lak + 3][lam] = rA.w;
                *(float4*)&sB[nb][lbk][lbn * 4] = rB;
                if (tid < 64) sWo[nb][tid] = rW;
            }
            __syncthreads();
        }

        // out_{t-1} store (B, T, D layout)
        if (t > 0) {
            out[(size_t)(m0 + om) * TT * DD + (size_t)te * DD + jt * 4 + od] =
                oacc + __ldg(&bout[te * DD + jt * 4 + od]);
        }

        if (t < TT) {
            // spill gates tile to smem for the cell update
            float v0, v1;
            upk2(a00, v0, v1); sg[(ty4 + 0) * SGP + tx4 + 0] = v0; sg[(ty4 + 0) * SGP + tx4 + 1] = v1;
            upk2(a01, v0, v1); sg[(ty4 + 0) * SGP + tx4 + 2] = v0; sg[(ty4 + 0) * SGP + tx4 + 3] = v1;
            upk2(a10, v0, v1); sg[(ty4 + 1) * SGP + tx4 + 0] = v0; sg[(ty4 + 1) * SGP + tx4 + 1] = v1;
            upk2(a11, v0, v1); sg[(ty4 + 1) * SGP + tx4 + 2] = v0; sg[(ty4 + 1) * SGP + tx4 + 3] = v1;
            upk2(a20, v0, v1); sg[(ty4 + 2) * SGP + tx4 + 0] = v0; sg[(ty4 + 2) * SGP + tx4 + 1] = v1;
            upk2(a21, v0, v1); sg[(ty4 + 2) * SGP + tx4 + 2] = v0; sg[(ty4 + 2) * SGP + tx4 + 3] = v1;
            upk2(a30, v0, v1); sg[(ty4 + 3) * SGP + tx4 + 0] = v0; sg[(ty4 + 3) * SGP + tx4 + 1] = v1;
            upk2(a31, v0, v1); sg[(ty4 + 3) * SGP + tx4 + 2] = v0; sg[(ty4 + 3) * SGP + tx4 + 3] = v1;
            __syncthreads();

            float* hn = g_h[(t + 1) & 1];
            const float xgi = sxg[jj], xgf = sxg[16 + jj], xgg = sxg[32 + jj], xgo = sxg[48 + jj];
            #pragma unroll
            for (int r = 0; r < 4; ++r) {
                const int m = mq * 4 + r;
                const float* row = &sg[m * SGP];
                float i = sigm(row[jj] + xgi);
                float f = sigm(row[16 + jj] + xgf);
                float g = tanhx(row[32 + jj] + xgg);
                float o = sigm(row[48 + jj] + xgo);
                float c = (r == 0) ? cc0 : (r == 1) ? cc1 : (r == 2) ? cc2 : cc3;
                c = f * c + i * g;
                if (r == 0) cc0 = c; else if (r == 1) cc1 = c; else if (r == 2) cc2 = c; else cc3 = c;
                __stcg(&hn[(size_t)(m0 + m) * HH + jt * 16 + jj], o * tanhx(c));
            }
            gridbar();
        }
    }
}

extern "C" void kernel_launch(void* const* d_in, const int* in_sizes, int n_in,
                              void* d_out, int out_size) {
    const float* z     = (const float*)d_in[0];
    const float* Wz    = (const float*)d_in[1];
    const float* bz    = (const float*)d_in[2];
    const float* token = (const float*)d_in[3];
    const float* Wi    = (const float*)d_in[4];
    const float* Wh    = (const float*)d_in[5];
    const float* bh    = (const float*)d_in[6];
    const float* Wout  = (const float*)d_in[7];
    const float* bout  = (const float*)d_in[8];
    float* out = (float*)d_out;

    lstm_reset_kernel<<<1, 1>>>();
    lstm_kernel<<<NCTA, NTHR>>>(z, Wz, bz, token, Wi, Wh, bh, Wout, bout, out);
}

// round 3
// speedup vs baseline: 4.9578x; 4.9578x over previous
#include <cuda_runtime.h>
#include <cuda_fp16.h>
#include <cstdint>

#define BB   256
#define TT   256
#define KTOK 128
#define HH   512
#define G4H  2048
#define DD   128

#define NCTA 128
#define NTHR 256

#define A_PITCH_B 272u                    // 128 k * 2B + 16B pad (conflict-free diag)
#define A_BUF_B   (128u * A_PITCH_B)      // 34816 per buffer
#define BG_PITCH_B 80u                    // 32 cols *2B + 16 pad
#define BO_PITCH_B 16u                    // 8 cols *2B

#define A_OFF   0u
#define BG_OFF  (2u * A_BUF_B)                    // 69632
#define BO_OFF  (BG_OFF + 512u * BG_PITCH_B)      // 110592
#define XG_OFF  (BO_OFF + 512u * BO_PITCH_B)      // 118784
#define SMEM_BYTES (XG_OFF + 128u)                // 118912

__device__ __half    g_h[2][BB * HH];
__device__ unsigned  g_bar;

__global__ void reset_kernel() { g_bar = 0u; }

__device__ __forceinline__ uint32_t smem_u32(const void* p) {
    uint32_t a;
    asm("{ .reg .u64 t; cvta.to.shared.u64 t, %1; cvt.u32.u64 %0, t; }" : "=r"(a) : "l"(p));
    return a;
}
__device__ __forceinline__ float sigm(float x)  { return 1.f / (1.f + __expf(-x)); }
__device__ __forceinline__ float tanhx(float x) { return 2.f / (1.f + __expf(-2.f * x)) - 1.f; }

__device__ __forceinline__ void ldsm_x4(uint32_t* r, uint32_t addr) {
    asm volatile("ldmatrix.sync.aligned.m8n8.x4.shared.b16 {%0,%1,%2,%3}, [%4];"
        : "=r"(r[0]), "=r"(r[1]), "=r"(r[2]), "=r"(r[3]) : "r"(addr));
}
__device__ __forceinline__ void ldsm_x2t(uint32_t* r, uint32_t addr) {
    asm volatile("ldmatrix.sync.aligned.m8n8.x2.trans.shared.b16 {%0,%1}, [%2];"
        : "=r"(r[0]), "=r"(r[1]) : "r"(addr));
}
__device__ __forceinline__ void mma16816(float* d, const uint32_t* a, const uint32_t* b) {
    asm volatile("mma.sync.aligned.m16n8k16.row.col.f32.f16.f16.f32 "
        "{%0,%1,%2,%3}, {%4,%5,%6,%7}, {%8,%9}, {%0,%1,%2,%3};"
        : "+f"(d[0]), "+f"(d[1]), "+f"(d[2]), "+f"(d[3])
        : "r"(a[0]), "r"(a[1]), "r"(a[2]), "r"(a[3]), "r"(b[0]), "r"(b[1]));
}

// grid barrier: 128 co-resident CTAs
__device__ __forceinline__ void gridbar() {
    __syncthreads();
    if (threadIdx.x == 0) {
        __threadfence();
        unsigned t = atomicAdd(&g_bar, 1u);
        unsigned target = (t / NCTA + 1u) * NCTA;
        while (*(volatile unsigned*)&g_bar < target) __nanosleep(64);
        __threadfence();
    }
    __syncthreads();
}

__global__ void __launch_bounds__(NTHR, 1) lstm_mma_kernel(
    const float* __restrict__ z,     const float* __restrict__ Wz,
    const float* __restrict__ bz,    const float* __restrict__ token,
    const float* __restrict__ Wi,    const float* __restrict__ Wh,
    const float* __restrict__ bh,    const float* __restrict__ Wout,
    const float* __restrict__ bout,  float* __restrict__ out)
{
    extern __shared__ char smem[];
    const uint32_t sb = smem_u32(smem);

    const int tid  = threadIdx.x;
    const int lane = tid & 31;
    const int w    = tid >> 5;            // warp 0..7  (m-tile)
    const int mh   = blockIdx.x & 1;      // batch half
    const int jg   = blockIdx.x >> 1;     // unit group 0..63
    const int m0   = mh * 128;
    const int j0   = jg * 8;

    // mma fragment geometry
    const int qr   = lane >> 2;           // 0..7
    const int qc   = lane & 3;            // 0..3
    const int row0 = w * 16 + qr;         // CTA-local rows row0, row0+8
    const int u0   = qc * 2;              // units u0, u0+1

    // A ldmatrix lane address
    const int grp = lane >> 3, li = lane & 7;
    const uint32_t aBase = sb + A_OFF + (uint32_t)(w * 16 + (grp & 1) * 8 + li) * A_PITCH_B
                         + (uint32_t)(grp >> 1) * 16u;
    // B ldmatrix lane addresses (lanes 0..15 meaningful)
    const int bl = lane & 15;
    const uint32_t bgBase = sb + BG_OFF + (uint32_t)bl * BG_PITCH_B;
    const uint32_t boBase = sb + BO_OFF + (uint32_t)bl * BO_PITCH_B;

    // A gmem<->smem staging map
    const int lm = tid >> 4;              // 0..15
    const int lc = tid & 15;              // granule 0..15

    float* sxg = (float*)(smem + XG_OFF);

    // ---------------- one-time init ----------------
    // zero B_out (pad cols stay zero forever)
    for (int i = tid; i < 512; i += NTHR) ((uint4*)(smem + BO_OFF))[i] = make_uint4(0, 0, 0, 0);

    // stage Wh slice -> fp16 smem [k][n], n = gate*8 + unit
    for (int idx = tid; idx < 512 * 32; idx += NTHR) {
        int k = idx >> 5, n = idx & 31;
        float v = __ldg(&Wh[(size_t)k * G4H + (n >> 3) * HH + j0 + (n & 7)]);
        *(__half*)(smem + BG_OFF + (uint32_t)k * BG_PITCH_B + (uint32_t)n * 2u) = __float2half_rn(v);
    }

    // x_gates = token @ Wi + bh for this CTA's 32 gate cols
    if (tid < 32) {
        int col = (tid >> 3) * HH + j0 + (tid & 7);
        float s = bh[col];
        #pragma unroll 4
        for (int k = 0; k < KTOK; ++k)
            s = fmaf(token[k], __ldg(&Wi[(size_t)k * G4H + col]), s);
        sxg[tid] = s;
    }

    // h0 = relu(z @ Wz + bz): thread -> (row tid>>1, 4 units)
    {
        const int r  = tid >> 1;
        const int ub = (tid & 1) * 4;
        float a[4];
        #pragma unroll
        for (int q = 0; q < 4; ++q) a[q] = bz[j0 + ub + q];
        const float* zr = z + (size_t)(m0 + r) * KTOK;
        #pragma unroll 4
        for (int k = 0; k < KTOK; ++k) {
            float zv = __ldg(zr + k);
            float4 w4 = __ldg((const float4*)&Wz[(size_t)k * HH + j0 + ub]);
            a[0] = fmaf(zv, w4.x, a[0]); a[1] = fmaf(zv, w4.y, a[1]);
            a[2] = fmaf(zv, w4.z, a[2]); a[3] = fmaf(zv, w4.w, a[3]);
        }
        __half2* hp = (__half2*)&g_h[0][(size_t)(m0 + r) * HH + j0 + ub];
        hp[0] = __floats2half2_rn(fmaxf(a[0], 0.f), fmaxf(a[1], 0.f));
        hp[1] = __floats2half2_rn(fmaxf(a[2], 0.f), fmaxf(a[3], 0.f));
    }
    gridbar();

    float c4[4] = {0.f, 0.f, 0.f, 0.f};

    // ---------------- sequential loop ----------------
    // iteration t: A = h_t; gates -> h_{t+1}; fused out_{t-1} = h_t @ Wo_{t-1}
    #pragma unroll 1
    for (int t = 0; t <= TT; ++t) {
        const __half* hsrc = g_h[t & 1];
        const int te = t - 1;

        // stage Wo_{t-1} (2 cols) into B_out rows
        if (t >= 1) {
            const float* Wo = Wout + (size_t)te * HH * DD + 2 * jg;
            #pragma unroll
            for (int r = 0; r < 2; ++r) {
                int k = tid * 2 + r;
                float2 wv = *(const float2*)(Wo + (size_t)k * DD);
                __half* p = (__half*)(smem + BO_OFF + (uint32_t)k * BO_PITCH_B);
                p[0] = __float2half_rn(wv.x);
                p[1] = __float2half_rn(wv.y);
            }
        }

        float acc[5][4];
        #pragma unroll
        for (int n = 0; n < 5; ++n)
            #pragma unroll
            for (int e = 0; e < 4; ++e) acc[n][e] = 0.f;

        // prologue: chunk0 -> buf0
        uint4 v[8];
        #pragma unroll
        for (int s = 0; s < 8; ++s)
            v[s] = __ldcg((const uint4*)&hsrc[(size_t)(m0 + lm + 16 * s) * HH + 0 * 128 + lc * 8]);
        #pragma unroll
        for (int s = 0; s < 8; ++s)
            *(uint4*)(smem + A_OFF + (uint32_t)(lm + 16 * s) * A_PITCH_B + (uint32_t)lc * 16u) = v[s];
        #pragma unroll
        for (int s = 0; s < 8; ++s)
            v[s] = __ldcg((const uint4*)&hsrc[(size_t)(m0 + lm + 16 * s) * HH + 1 * 128 + lc * 8]);
        __syncthreads();

        #pragma unroll
        for (int kc = 0; kc < 4; ++kc) {
            const uint32_t buf = (uint32_t)(kc & 1);
            if (kc < 3) {  // store chunk kc+1 into other buffer
                const uint32_t nb = buf ^ 1u;
                #pragma unroll
                for (int s = 0; s < 8; ++s)
                    *(uint4*)(smem + A_OFF + nb * A_BUF_B + (uint32_t)(lm + 16 * s) * A_PITCH_B + (uint32_t)lc * 16u) = v[s];
            }
            if (kc < 2) {  // prefetch chunk kc+2
                #pragma unroll
                for (int s = 0; s < 8; ++s)
                    v[s] = __ldcg((const uint4*)&hsrc[(size_t)(m0 + lm + 16 * s) * HH + (kc + 2) * 128 + lc * 8]);
            }
            // compute on buf
            const uint32_t aA  = aBase + buf * A_BUF_B;
            const uint32_t bgA = bgBase + (uint32_t)(kc * 128) * BG_PITCH_B;
            const uint32_t boA = boBase + (uint32_t)(kc * 128) * BO_PITCH_B;
            #pragma unroll
            for (int kf = 0; kf < 8; ++kf) {
                uint32_t a[4], b[2];
                ldsm_x4(a, aA + (uint32_t)kf * 32u);
                #pragma unroll
                for (int nt = 0; nt < 4; ++nt) {
                    ldsm_x2t(b, bgA + (uint32_t)(kf * 16) * BG_PITCH_B + (uint32_t)nt * 16u);
                    mma16816(acc[nt], a, b);
                }
                ldsm_x2t(b, boA + (uint32_t)(kf * 16) * BO_PITCH_B);
                mma16816(acc[4], a, b);
            }
            if (kc < 3) __syncthreads();
        }

        // ---- out store ----
        if (qc == 0 && t >= 1) {
            const float2 bo = *(const float2*)&bout[te * DD + 2 * jg];
            float2 o0 = make_float2(acc[4][0] + bo.x, acc[4][1] + bo.y);
            float2 o1 = make_float2(acc[4][2] + bo.x, acc[4][3] + bo.y);
            *(float2*)&out[(size_t)(m0 + row0) * TT * DD + (size_t)te * DD + 2 * jg] = o0;
            *(float2*)&out[(size_t)(m0 + row0 + 8) * TT * DD + (size_t)te * DD + 2 * jg] = o1;
        }

        // ---- cell update (registers) + h store ----
        if (t < TT) {
            float hv[4];
            #pragma unroll
            for (int e = 0; e < 4; ++e) {
                const int u = u0 + (e & 1);
                float gi = sigm (acc[0][e] + sxg[u]);
                float gf = sigm (acc[1][e] + sxg[8 + u]);
                float gg = tanhx(acc[2][e] + sxg[16 + u]);
                float go = sigm (acc[3][e] + sxg[24 + u]);
                float cv = gf * c4[e] + gi * gg;
                c4[e] = cv;
                hv[e] = go * tanhx(cv);
            }
            __half* hdst = &g_h[(t + 1) & 1][0];
            *(__half2*)&hdst[(size_t)(m0 + row0) * HH + j0 + u0]     = __floats2half2_rn(hv[0], hv[1]);
            *(__half2*)&hdst[(size_t)(m0 + row0 + 8) * HH + j0 + u0] = __floats2half2_rn(hv[2], hv[3]);
            gridbar();
        }
    }
}

extern "C" void kernel_launch(void* const* d_in, const int* in_sizes, int n_in,
                              void* d_out, int out_size) {
    const float* z     = (const float*)d_in[0];
    const float* Wz    = (const float*)d_in[1];
    const float* bz    = (const float*)d_in[2];
    const float* token = (const float*)d_in[3];
    const float* Wi    = (const float*)d_in[4];
    const float* Wh    = (const float*)d_in[5];
    const float* bh    = (const float*)d_in[6];
    const float* Wout  = (const float*)d_in[7];
    const float* bout  = (const float*)d_in[8];
    float* out = (float*)d_out;

    cudaFuncSetAttribute(lstm_mma_kernel, cudaFuncAttributeMaxDynamicSharedMemorySize, SMEM_BYTES);
    reset_kernel<<<1, 1>>>();
    lstm_mma_kernel<<<NCTA, NTHR, SMEM_BYTES>>>(z, Wz, bz, token, Wi, Wh, bh, Wout, bout, out);
}